// round 16
// baseline (speedup 1.0000x reference)
#include <cuda_runtime.h>
#include <math.h>

#define NB     256
#define NPB    65536
#define NBATCH 4
#define EPS    1e-10f
#define INV_N  (1.0f / 65536.0f)
#define MSCALE 2048.0f               // 2^11 marginal fixed-point (16-bit fields)
#define INV_MSCALE (1.0f / 2048.0f)
#define JSCALE 4096.0f               // 2^12 joint fixed-point (16-bit fields)
#define INV_JSCALE (1.0f / 4096.0f)

// ---------- persistent scratch (zero-init at load; re-zeroed every call) ----------
// Packed 2x2-patch joint: g_J[b][i0][j0] u64 =
//   bits[ 0:16) X -> cell (i0,  j0)     bits[16:32) Y -> cell (i0,  j0+1)
//   bits[32:48) Z -> cell (i0+1,j0)     bits[48:64) W -> cell (i0+1,j0+1)
// cell(i,j) = X[i][j] + Y[i][j-1] + Z[i-1][j] + W[i-1][j-1], scaled 2^-12.
// Per-field capacity 65535/4096 ~ 16.0 vs ~Poisson(1) hits/cell: no carry.
__device__ unsigned long long g_J[NBATCH][NB][NB];   // 2 MB
__device__ float  g_h1[NBATCH * NB];
__device__ float  g_h2[NBATCH * NB];
__device__ double g_sj[NBATCH];
__device__ double g_ej[NBATCH];
__device__ float  g_H1[NBATCH], g_H2[NBATCH];
__device__ unsigned g_bar1;

// ================= kernel 1: sparse KDE accumulation =================
// sigma=0.1 in bin units: only the two straddling bins carry weight (third
// bin <= e^-50 ~ 2e-22 relative). Joint: ONE red.add.u64 per pixel (four
// 16-bit fields). Marginals: ONE u32 smem atomic per (pixel, image).
// 512 CTAs x 256 thr x 2 px/thread: 28 warps/SM for latency hiding.
#define THREADS_ACC 256
#define PIX_PER_CTA 512

__global__ __launch_bounds__(THREADS_ACC)
void mi_accum_kernel(const float* __restrict__ in1, const float* __restrict__ in2) {
    __shared__ unsigned shp1[NB];
    __shared__ unsigned shp2[NB];
    int tid = threadIdx.x;
    int base = blockIdx.x * PIX_PER_CTA;
    int b = base >> 16;

    float2 a = __ldcs((const float2*)(in1 + base) + tid);
    float2 c = __ldcs((const float2*)(in2 + base) + tid);

    shp1[tid] = 0u;
    shp2[tid] = 0u;
    __syncthreads();

    const float xs1[2] = {a.x, a.y};
    const float xs2[2] = {c.x, c.y};

#pragma unroll
    for (int k = 0; k < 2; k++) {
        float x1 = xs1[k] * 255.0f;
        float x2 = xs2[k] * 255.0f;
        int i0 = min((int)floorf(x1), NB - 2);
        int j0 = min((int)floorf(x2), NB - 2);
        float f1 = x1 - (float)i0, q1 = 1.0f - f1;
        float f2 = x2 - (float)j0, q2 = 1.0f - f2;
        float wa1 = __expf(-50.0f * f1 * f1);
        float wb1 = __expf(-50.0f * q1 * q1);
        float wa2 = __expf(-50.0f * f2 * f2);
        float wb2 = __expf(-50.0f * q2 * q2);

        unsigned long long pk =
              (unsigned long long)__float2uint_rn(wa1 * wa2 * JSCALE)
            | ((unsigned long long)__float2uint_rn(wa1 * wb2 * JSCALE) << 16)
            | ((unsigned long long)__float2uint_rn(wb1 * wa2 * JSCALE) << 32)
            | ((unsigned long long)__float2uint_rn(wb1 * wb2 * JSCALE) << 48);
        atomicAdd(&g_J[b][i0][j0], pk);

        unsigned p1 = __float2uint_rn(wa1 * MSCALE)
                    | (__float2uint_rn(wb1 * MSCALE) << 16);
        unsigned p2 = __float2uint_rn(wa2 * MSCALE)
                    | (__float2uint_rn(wb2 * MSCALE) << 16);
        atomicAdd(&shp1[i0], p1);
        atomicAdd(&shp2[j0], p2);
    }

    __syncthreads();
    unsigned s1 = shp1[tid];
    unsigned s2 = shp2[tid];
    unsigned h1p = (tid > 0) ? (shp1[tid - 1] >> 16) : 0u;
    unsigned h2p = (tid > 0) ? (shp2[tid - 1] >> 16) : 0u;
    atomicAdd(&g_h1[b * NB + tid], (float)((s1 & 0xFFFFu) + h1p) * INV_MSCALE);
    atomicAdd(&g_h2[b * NB + tid], (float)((s2 & 0xFFFFu) + h2p) * INV_MSCALE);
}

// ================= kernel 2: PDL reduce + combine + re-zero =================
// CTA (rb, sub) owns cell rows [4sub..4sub+3]. Z/W of interior rows are
// staged via smem; only the boundary row (4sub-1) high-halves come from L2.
// Zero ownership: rows 4sub..4sub+2 fully zeroed here; row 4sub+3 low halves
// here / high halves by CTA sub+1; row 4sub-1 high halves here. Every byte
// zeroed once, by a thread in the CTA that read it, after __syncthreads.

__device__ __forceinline__ float2 fred256x2(float va, float vb, float2* sred) {
#pragma unroll
    for (int o = 16; o; o >>= 1) {
        va += __shfl_xor_sync(0xffffffffu, va, o);
        vb += __shfl_xor_sync(0xffffffffu, vb, o);
    }
    int wid = threadIdx.x >> 5, lid = threadIdx.x & 31;
    if (lid == 0) sred[wid] = make_float2(va, vb);
    __syncthreads();
    if (threadIdx.x < 32) {
        float ra = (threadIdx.x < 8) ? sred[threadIdx.x].x : 0.0f;
        float rb = (threadIdx.x < 8) ? sred[threadIdx.x].y : 0.0f;
#pragma unroll
        for (int o = 4; o; o >>= 1) {
            ra += __shfl_xor_sync(0xffffffffu, ra, o);
            rb += __shfl_xor_sync(0xffffffffu, rb, o);
        }
        if (threadIdx.x == 0) sred[0] = make_float2(ra, rb);
    }
    __syncthreads();
    float2 out = sred[0];
    __syncthreads();
    return out;
}

__global__ __launch_bounds__(256)
void mi_reduce_final_kernel(float* __restrict__ out) {
    __shared__ float2 sred[8];
    __shared__ unsigned szw[4][NB];          // staged high halves (Z|W) per row
    int tid = threadIdx.x;
    int rb  = blockIdx.x >> 6;
    int sub = blockIdx.x & 63;
    int t   = tid >> 6;                      // 0..3: row within CTA
    int row = 4 * sub + t;
    int c0  = (tid & 63) * 4;

    unsigned long long* Jrow = &g_J[rb][row][0];

    // ---- wait for accum completion (PDL implicit trigger) ----
    asm volatile("griddepcontrol.wait;" ::: "memory");

    ulonglong2 a01 = *(ulonglong2*)(Jrow + c0);
    ulonglong2 a23 = *(ulonglong2*)(Jrow + c0 + 2);
    unsigned ap = (c0 > 0) ? ((unsigned*)(Jrow + c0 - 1))[0] : 0u;   // Y = >>16

    szw[t][c0]     = (unsigned)(a01.x >> 32);
    szw[t][c0 + 1] = (unsigned)(a01.y >> 32);
    szw[t][c0 + 2] = (unsigned)(a23.x >> 32);
    szw[t][c0 + 3] = (unsigned)(a23.y >> 32);

    bool have_b = (row > 0);
    unsigned long long* Brow = &g_J[rb][have_b ? row - 1 : 0][0];
    unsigned bh0 = 0, bh1 = 0, bh2 = 0, bh3 = 0, bhp = 0;
    if (t == 0 && have_b) {                  // boundary row: global high halves
        bh0 = ((unsigned*)(Brow + c0))[1];
        bh1 = ((unsigned*)(Brow + c0 + 1))[1];
        bh2 = ((unsigned*)(Brow + c0 + 2))[1];
        bh3 = ((unsigned*)(Brow + c0 + 3))[1];
        bhp = (c0 > 0) ? ((unsigned*)(Brow + c0 - 1))[1] : 0u;
    }
    __syncthreads();                          // global reads + staging done
    if (t > 0) {
        bh0 = szw[t - 1][c0];
        bh1 = szw[t - 1][c0 + 1];
        bh2 = szw[t - 1][c0 + 2];
        bh3 = szw[t - 1][c0 + 3];
        bhp = (c0 > 0) ? szw[t - 1][c0 - 1] : 0u;
    }

    // re-zero (ownership policy above)
    if (t < 3) {
        ulonglong2 zz = make_ulonglong2(0ull, 0ull);
        *(ulonglong2*)(Jrow + c0)     = zz;
        *(ulonglong2*)(Jrow + c0 + 2) = zz;
    } else {                                  // row 4sub+3: low halves only
        ((unsigned*)(Jrow + c0))[0]     = 0u;
        ((unsigned*)(Jrow + c0 + 1))[0] = 0u;
        ((unsigned*)(Jrow + c0 + 2))[0] = 0u;
        ((unsigned*)(Jrow + c0 + 3))[0] = 0u;
    }
    if (t == 0 && have_b) {                   // row 4sub-1: high halves only
        ((unsigned*)(Brow + c0))[1]     = 0u;
        ((unsigned*)(Brow + c0 + 1))[1] = 0u;
        ((unsigned*)(Brow + c0 + 2))[1] = 0u;
        ((unsigned*)(Brow + c0 + 3))[1] = 0u;
    }

    // fold: exact integer sums (max ~250K << 2^24), then scale
    unsigned v0 = (unsigned)(a01.x & 0xFFFFu) + (ap >> 16)
                + (bh0 & 0xFFFFu) + (bhp >> 16);
    unsigned v1 = (unsigned)(a01.y & 0xFFFFu) + (unsigned)((a01.x >> 16) & 0xFFFFu)
                + (bh1 & 0xFFFFu) + (bh0 >> 16);
    unsigned v2 = (unsigned)(a23.x & 0xFFFFu) + (unsigned)((a01.y >> 16) & 0xFFFFu)
                + (bh2 & 0xFFFFu) + (bh1 >> 16);
    unsigned v3 = (unsigned)(a23.y & 0xFFFFu) + (unsigned)((a23.x >> 16) & 0xFFFFu)
                + (bh3 & 0xFFFFu) + (bh2 >> 16);

    float f0 = (float)v0 * INV_JSCALE;
    float f1 = (float)v1 * INV_JSCALE;
    float f2 = (float)v2 * INV_JSCALE;
    float f3 = (float)v3 * INV_JSCALE;

    float sj = (float)(v0 + v1 + v2 + v3) * INV_JSCALE;
    float ej = f0 * __log2f(f0 + EPS)
             + f1 * __log2f(f1 + EPS)
             + f2 * __log2f(f2 + EPS)
             + f3 * __log2f(f3 + EPS);

    float2 se = fred256x2(sj, ej, sred);
    if (tid == 0) {
        atomicAdd(&g_sj[rb], (double)se.x);
        atomicAdd(&g_ej[rb], (double)se.y);
    }

    // marginals: exact reference math, one CTA per batch
    if (sub == 0) {
        float h1 = __ldcg(&g_h1[rb * NB + tid]);
        float h2 = __ldcg(&g_h2[rb * NB + tid]);
        g_h1[rb * NB + tid] = 0.0f;           // same-thread read-then-zero
        g_h2[rb * NB + tid] = 0.0f;
        float m1 = h1 * INV_N;
        float m2 = h2 * INV_N;
        float2 S = fred256x2(m1, m2, sred);
        float p1v = m1 / (S.x + EPS);
        float p2v = m2 / (S.y + EPS);
        float2 E = fred256x2(p1v * __log2f(p1v + EPS),
                             p2v * __log2f(p2v + EPS), sred);
        if (tid == 0) { g_H1[rb] = -E.x; g_H2[rb] = -E.y; }
    }

    // last-block combine + reset
    __threadfence();
    __syncthreads();
    if (tid == 0) {
        unsigned tk = atomicAdd(&g_bar1, 1u);
        if (tk == 255u) {
            __threadfence();
            double acc = 0.0;
#pragma unroll
            for (int bb = 0; bb < NBATCH; bb++) {
                double Sj = g_sj[bb];
                double Ej = g_ej[bb];
                double den = Sj + (double)EPS;
                // Hj = -sum q*log2(q+eps), q=j/(Sj+eps), factored single-pass
                double Hj = -(Ej - Sj * log2(den)) / den;
                double H1 = (double)g_H1[bb];
                double H2 = (double)g_H2[bb];
                acc += 2.0 * (H1 + H2 - Hj) / (H1 + H2);
                g_sj[bb] = 0.0; g_ej[bb] = 0.0;
                g_H1[bb] = 0.0f; g_H2[bb] = 0.0f;
            }
            out[0] = (float)(acc * 0.25);
            g_bar1 = 0u;
        }
    }
}

// ================= launch: 2 kernels, second via PDL =================
extern "C" void kernel_launch(void* const* d_in, const int* in_sizes, int n_in,
                              void* d_out, int out_size) {
    const float* in1 = (const float*)d_in[0];
    const float* in2 = (const float*)d_in[1];
    float* out = (float*)d_out;

    mi_accum_kernel<<<(NBATCH * NPB) / PIX_PER_CTA, THREADS_ACC>>>(in1, in2);

    cudaLaunchConfig_t cfg = {};
    cfg.gridDim  = dim3(256, 1, 1);
    cfg.blockDim = dim3(256, 1, 1);
    cudaLaunchAttribute attr[1];
    attr[0].id = cudaLaunchAttributeProgrammaticStreamSerialization;
    attr[0].val.programmaticStreamSerializationAllowed = 1;
    cfg.attrs = attr;
    cfg.numAttrs = 1;
    cudaError_t e = cudaLaunchKernelEx(&cfg, mi_reduce_final_kernel, out);
    if (e != cudaSuccess) {
        // PDL rejected -> plain launch fallback
        mi_reduce_final_kernel<<<256, 256>>>(out);
    }
}